// round 8
// baseline (speedup 1.0000x reference)
#include <cuda_runtime.h>

// PixCorr: per-row Pearson correlation over [256, 196608] fp32 rows, then
// mean over rows.
//
// Single persistent-style launch with STATIC perfect balance:
//  - The full stream of TOTVEC = 256*49152 = 12,582,912 float4 pairs is
//    partitioned contiguously over exactly 148 CTAs (one per SM, one wave):
//    CTA c owns [c*TOTVEC/148, (c+1)*TOTVEC/148)  (+-1 vec).
//  - A CTA's span crosses at most 2 row boundaries -> at most 3 sub-spans,
//    each a long uninterrupted streaming loop (plain cached float4 loads,
//    5 running sums), block-reduced into a deterministic slot
//    g_part[c*3 + (row - first_row(c))].
//  - Last CTA (done ticket) reassembles each row from its <=2 contributing
//    CTAs in fixed order, computes corr per row, means them, writes d_out[0],
//    resets the ticket for graph replay determinism.

#define NROWS    256
#define D_ELEMS  196608                      // 3*256*256
#define NVEC     (D_ELEMS / 4)               // 49152 float4 per row
#define TOTVEC   ((unsigned long long)NROWS * NVEC)  // 12,582,912
#define GRID     148
#define THREADS  1024
#define SLOTS    3                           // max rows touched per CTA span
#define EPS      1e-6f

__device__ float        g_part[GRID * SLOTS][5];
__device__ unsigned int g_done;              // zero-initialized

__device__ __forceinline__ float warp_sum(float v) {
    v += __shfl_xor_sync(0xFFFFFFFFu, v, 16);
    v += __shfl_xor_sync(0xFFFFFFFFu, v, 8);
    v += __shfl_xor_sync(0xFFFFFFFFu, v, 4);
    v += __shfl_xor_sync(0xFFFFFFFFu, v, 2);
    v += __shfl_xor_sync(0xFFFFFFFFu, v, 1);
    return v;
}

// start vec of CTA c's span
__device__ __forceinline__ unsigned int span_start(unsigned int c) {
    return (unsigned int)(((unsigned long long)c * TOTVEC) / GRID);
}
// CTA whose span contains vec v
__device__ __forceinline__ unsigned int cta_of(unsigned int v) {
    return (unsigned int)((((unsigned long long)v + 1ull) * GRID - 1ull) / TOTVEC);
}

__global__ __launch_bounds__(THREADS, 1)
void pixcorr_flat_kernel(const float* __restrict__ preds,
                         const float* __restrict__ targets,
                         float* __restrict__ out) {
    __shared__ float sh[5][THREADS / 32];
    __shared__ int   s_is_last;
    const int lane = threadIdx.x & 31;
    const int wid  = threadIdx.x >> 5;
    const unsigned int c = blockIdx.x;

    const unsigned int span_lo = span_start(c);
    const unsigned int span_hi = span_start(c + 1);
    const unsigned int row_first = span_lo / NVEC;

    const float4* __restrict__ zall = reinterpret_cast<const float4*>(targets);
    const float4* __restrict__ ball = reinterpret_cast<const float4*>(preds);

    unsigned int pos  = span_lo;
    int          slot = 0;
    while (pos < span_hi) {
        const unsigned int row_end = (pos / NVEC + 1u) * NVEC;
        const unsigned int sub_end = (row_end < span_hi) ? row_end : span_hi;
        const int len = (int)(sub_end - pos);

        const float4* __restrict__ z4 = zall + pos;
        const float4* __restrict__ b4 = ball + pos;

        float sz = 0.f, sb = 0.f, szz = 0.f, sbb = 0.f, szb = 0.f;

        // Long uninterrupted streaming loop (~28-48 iters/thread), plain
        // cached coalesced 128-bit loads, high MLP via unroll.
        #pragma unroll 4
        for (int i = threadIdx.x; i < len; i += THREADS) {
            float4 zv = z4[i];
            float4 bv = b4[i];
            sz  += (zv.x + zv.y) + (zv.z + zv.w);
            sb  += (bv.x + bv.y) + (bv.z + bv.w);
            szz  = fmaf(zv.x, zv.x, fmaf(zv.y, zv.y, fmaf(zv.z, zv.z, fmaf(zv.w, zv.w, szz))));
            sbb  = fmaf(bv.x, bv.x, fmaf(bv.y, bv.y, fmaf(bv.z, bv.z, fmaf(bv.w, bv.w, sbb))));
            szb  = fmaf(zv.x, bv.x, fmaf(zv.y, bv.y, fmaf(zv.z, bv.z, fmaf(zv.w, bv.w, szb))));
        }

        sz  = warp_sum(sz);
        sb  = warp_sum(sb);
        szz = warp_sum(szz);
        sbb = warp_sum(sbb);
        szb = warp_sum(szb);

        if (lane == 0) {
            sh[0][wid] = sz;  sh[1][wid] = sb;
            sh[2][wid] = szz; sh[3][wid] = sbb; sh[4][wid] = szb;
        }
        __syncthreads();

        if (threadIdx.x < 32) {
            float a0 = warp_sum(sh[0][lane]);
            float a1 = warp_sum(sh[1][lane]);
            float a2 = warp_sum(sh[2][lane]);
            float a3 = warp_sum(sh[3][lane]);
            float a4 = warp_sum(sh[4][lane]);
            if (lane == 0) {
                const int idx = (int)c * SLOTS + slot;
                g_part[idx][0] = a0;
                g_part[idx][1] = a1;
                g_part[idx][2] = a2;
                g_part[idx][3] = a3;
                g_part[idx][4] = a4;
            }
        }
        __syncthreads();

        slot++;
        pos = sub_end;
    }
    (void)row_first;

    // Completion ticket.
    if (threadIdx.x == 0) {
        __threadfence();
        unsigned int d = atomicAdd(&g_done, 1u);
        s_is_last = (d == GRID - 1u) ? 1 : 0;
    }
    __syncthreads();

    if (s_is_last) {
        __threadfence();  // observe all CTAs' g_part writes
        __shared__ float shm[THREADS / 32];
        float corr = 0.f;
        if (threadIdx.x < NROWS) {
            const unsigned int r = threadIdx.x;
            const unsigned int v0 = r * NVEC;
            const unsigned int v1 = v0 + NVEC - 1u;
            const unsigned int c0 = cta_of(v0);
            const unsigned int c1 = cta_of(v1);
            float a0 = 0.f, a1 = 0.f, a2 = 0.f, a3 = 0.f, a4 = 0.f;
            // Fixed combine order c0 -> c1 (<= 2 contributors).
            for (unsigned int cc = c0; cc <= c1; cc++) {
                const unsigned int rf = span_start(cc) / NVEC;
                const int idx = (int)cc * SLOTS + (int)(r - rf);
                a0 += g_part[idx][0];
                a1 += g_part[idx][1];
                a2 += g_part[idx][2];
                a3 += g_part[idx][3];
                a4 += g_part[idx][4];
            }
            const float invD = 1.0f / (float)D_ELEMS;
            float cov = a4 - a0 * a1 * invD;
            float vz  = fmaxf(a2 - a0 * a0 * invD, 0.f);
            float vb  = fmaxf(a3 - a1 * a1 * invD, 0.f);
            corr = cov / (sqrtf(vz) * sqrtf(vb) + EPS);
        }
        corr = warp_sum(corr);
        if (lane == 0) shm[wid] = corr;
        __syncthreads();
        if (threadIdx.x == 0) {
            float s = 0.f;
            #pragma unroll
            for (int i = 0; i < NROWS / 32; i++) s += shm[i];
            out[0] = s * (1.0f / (float)NROWS);
            g_done = 0;             // reset for next graph replay
            __threadfence();
        }
    }
}

extern "C" void kernel_launch(void* const* d_in, const int* in_sizes, int n_in,
                              void* d_out, int out_size) {
    const float* preds   = (const float*)d_in[0];
    const float* targets = (const float*)d_in[1];
    float* out = (float*)d_out;

    pixcorr_flat_kernel<<<GRID, THREADS>>>(preds, targets, out);
}

// round 9
// speedup vs baseline: 1.0314x; 1.0314x over previous
#include <cuda_runtime.h>

// PixCorr: per-row Pearson correlation over [256, 196608] fp32 rows, then
// mean over rows.
//
// Mainloop is byte-for-byte the R2 row kernel (fastest streamer measured:
// plain cached float4 loads, one CTA per row, 256 x 1024, unroll 4).
// Only change vs R2: the second launch is replaced by a last-CTA-done
// epilogue (atomic ticket + fence), so the ~2-4us mean-kernel tail is gone.

#define NROWS   256
#define D_ELEMS 196608          // 3*256*256
#define NVEC    (D_ELEMS / 4)   // 49152 float4 per row
#define THREADS 1024
#define EPS     1e-6f

__device__ float        g_corr[NROWS];
__device__ unsigned int g_ticket;   // zero-initialized at module load

__device__ __forceinline__ float warp_sum(float v) {
    v += __shfl_xor_sync(0xFFFFFFFFu, v, 16);
    v += __shfl_xor_sync(0xFFFFFFFFu, v, 8);
    v += __shfl_xor_sync(0xFFFFFFFFu, v, 4);
    v += __shfl_xor_sync(0xFFFFFFFFu, v, 2);
    v += __shfl_xor_sync(0xFFFFFFFFu, v, 1);
    return v;
}

__global__ __launch_bounds__(THREADS, 1)
void pixcorr_fused_kernel(const float* __restrict__ preds,
                          const float* __restrict__ targets,
                          float* __restrict__ out) {
    const int row = blockIdx.x;
    const float4* __restrict__ z4 =
        reinterpret_cast<const float4*>(targets + (size_t)row * D_ELEMS);
    const float4* __restrict__ b4 =
        reinterpret_cast<const float4*>(preds + (size_t)row * D_ELEMS);

    float sz = 0.f, sb = 0.f, szz = 0.f, sbb = 0.f, szb = 0.f;

    // 48 iterations per thread, fully coalesced plain cached float4 loads.
    // (R2-proven fast path: no cache hints, ptxas batches the LDG.128s.)
    #pragma unroll 4
    for (int i = threadIdx.x; i < NVEC; i += THREADS) {
        float4 zv = z4[i];
        float4 bv = b4[i];
        sz  += (zv.x + zv.y) + (zv.z + zv.w);
        sb  += (bv.x + bv.y) + (bv.z + bv.w);
        szz  = fmaf(zv.x, zv.x, fmaf(zv.y, zv.y, fmaf(zv.z, zv.z, fmaf(zv.w, zv.w, szz))));
        sbb  = fmaf(bv.x, bv.x, fmaf(bv.y, bv.y, fmaf(bv.z, bv.z, fmaf(bv.w, bv.w, sbb))));
        szb  = fmaf(zv.x, bv.x, fmaf(zv.y, bv.y, fmaf(zv.z, bv.z, fmaf(zv.w, bv.w, szb))));
    }

    sz  = warp_sum(sz);
    sb  = warp_sum(sb);
    szz = warp_sum(szz);
    sbb = warp_sum(sbb);
    szb = warp_sum(szb);

    __shared__ float sh[5][THREADS / 32];
    __shared__ int   s_is_last;
    const int lane = threadIdx.x & 31;
    const int wid  = threadIdx.x >> 5;
    if (lane == 0) {
        sh[0][wid] = sz;  sh[1][wid] = sb;
        sh[2][wid] = szz; sh[3][wid] = sbb; sh[4][wid] = szb;
    }
    __syncthreads();

    if (threadIdx.x < 32) {
        float a0 = warp_sum(sh[0][lane]);
        float a1 = warp_sum(sh[1][lane]);
        float a2 = warp_sum(sh[2][lane]);
        float a3 = warp_sum(sh[3][lane]);
        float a4 = warp_sum(sh[4][lane]);
        if (lane == 0) {
            const float invD = 1.0f / (float)D_ELEMS;
            float cov = a4 - a0 * a1 * invD;
            float vz  = fmaxf(a2 - a0 * a0 * invD, 0.f);
            float vb  = fmaxf(a3 - a1 * a1 * invD, 0.f);
            g_corr[row] = cov / (sqrtf(vz) * sqrtf(vb) + EPS);

            __threadfence();
            unsigned int t = atomicAdd(&g_ticket, 1u);
            s_is_last = (t == NROWS - 1u) ? 1 : 0;
        }
    }
    __syncthreads();

    if (s_is_last) {
        __threadfence();  // observe all other CTAs' g_corr writes
        float v = 0.f;
        if (threadIdx.x < NROWS) v = g_corr[threadIdx.x];
        v = warp_sum(v);
        __shared__ float shm[THREADS / 32];
        if (lane == 0) shm[wid] = v;
        __syncthreads();
        if (threadIdx.x == 0) {
            float s = 0.f;
            #pragma unroll
            for (int i = 0; i < NROWS / 32; i++) s += shm[i];
            out[0] = s * (1.0f / (float)NROWS);
            g_ticket = 0;           // reset for next graph replay
            __threadfence();
        }
    }
}

extern "C" void kernel_launch(void* const* d_in, const int* in_sizes, int n_in,
                              void* d_out, int out_size) {
    const float* preds   = (const float*)d_in[0];
    const float* targets = (const float*)d_in[1];
    float* out = (float*)d_out;

    pixcorr_fused_kernel<<<NROWS, THREADS>>>(preds, targets, out);
}

// round 10
// speedup vs baseline: 1.0770x; 1.0442x over previous
#include <cuda_runtime.h>

// PixCorr: per-row Pearson correlation over [256, 196608] fp32 rows, then
// mean over rows.
//
// Structure = R2 exactly (the best measured total, 62.2us): two kernels,
// plain cached float4 loads, one CTA per row (256 x 1024). The only change:
// the mean kernel is launched with PDL (programmatic stream serialization)
// and opens with cudaGridDependencySynchronize(), so its launch latency
// overlaps the row kernel's execution instead of serializing after it.

#define NROWS   256
#define D_ELEMS 196608          // 3*256*256
#define NVEC    (D_ELEMS / 4)   // 49152 float4 per row
#define THREADS 1024
#define EPS     1e-6f

__device__ float g_corr[NROWS];

__device__ __forceinline__ float warp_sum(float v) {
    v += __shfl_xor_sync(0xFFFFFFFFu, v, 16);
    v += __shfl_xor_sync(0xFFFFFFFFu, v, 8);
    v += __shfl_xor_sync(0xFFFFFFFFu, v, 4);
    v += __shfl_xor_sync(0xFFFFFFFFu, v, 2);
    v += __shfl_xor_sync(0xFFFFFFFFu, v, 1);
    return v;
}

__global__ __launch_bounds__(THREADS, 1)
void pixcorr_row_kernel(const float* __restrict__ preds,
                        const float* __restrict__ targets) {
    const int row = blockIdx.x;
    const float4* __restrict__ z4 =
        reinterpret_cast<const float4*>(targets + (size_t)row * D_ELEMS);
    const float4* __restrict__ b4 =
        reinterpret_cast<const float4*>(preds + (size_t)row * D_ELEMS);

    float sz = 0.f, sb = 0.f, szz = 0.f, sbb = 0.f, szb = 0.f;

    // 48 iterations per thread, fully coalesced plain cached float4 loads.
    #pragma unroll 4
    for (int i = threadIdx.x; i < NVEC; i += THREADS) {
        float4 zv = z4[i];
        float4 bv = b4[i];
        sz  += (zv.x + zv.y) + (zv.z + zv.w);
        sb  += (bv.x + bv.y) + (bv.z + bv.w);
        szz  = fmaf(zv.x, zv.x, fmaf(zv.y, zv.y, fmaf(zv.z, zv.z, fmaf(zv.w, zv.w, szz))));
        sbb  = fmaf(bv.x, bv.x, fmaf(bv.y, bv.y, fmaf(bv.z, bv.z, fmaf(bv.w, bv.w, sbb))));
        szb  = fmaf(zv.x, bv.x, fmaf(zv.y, bv.y, fmaf(zv.z, bv.z, fmaf(zv.w, bv.w, szb))));
    }

    sz  = warp_sum(sz);
    sb  = warp_sum(sb);
    szz = warp_sum(szz);
    sbb = warp_sum(sbb);
    szb = warp_sum(szb);

    __shared__ float sh[5][THREADS / 32];
    const int lane = threadIdx.x & 31;
    const int wid  = threadIdx.x >> 5;
    if (lane == 0) {
        sh[0][wid] = sz;  sh[1][wid] = sb;
        sh[2][wid] = szz; sh[3][wid] = sbb; sh[4][wid] = szb;
    }
    __syncthreads();

    if (threadIdx.x < 32) {
        float a0 = warp_sum(sh[0][lane]);
        float a1 = warp_sum(sh[1][lane]);
        float a2 = warp_sum(sh[2][lane]);
        float a3 = warp_sum(sh[3][lane]);
        float a4 = warp_sum(sh[4][lane]);
        if (lane == 0) {
            const float invD = 1.0f / (float)D_ELEMS;
            float cov = a4 - a0 * a1 * invD;
            float vz  = fmaxf(a2 - a0 * a0 * invD, 0.f);
            float vb  = fmaxf(a3 - a1 * a1 * invD, 0.f);
            g_corr[row] = cov / (sqrtf(vz) * sqrtf(vb) + EPS);
        }
    }
}

__global__ void pixcorr_mean_kernel(float* __restrict__ out) {
    // PDL: wait for the primary grid's completion + memory flush before
    // reading g_corr. If launched without PDL this is a no-op-equivalent
    // (dependency already satisfied by stream order).
    cudaGridDependencySynchronize();

    // 256 threads = 8 warps
    float v = g_corr[threadIdx.x];
    v = warp_sum(v);
    __shared__ float sh[8];
    const int lane = threadIdx.x & 31;
    const int wid  = threadIdx.x >> 5;
    if (lane == 0) sh[wid] = v;
    __syncthreads();
    if (threadIdx.x == 0) {
        float s = 0.f;
        #pragma unroll
        for (int i = 0; i < 8; i++) s += sh[i];
        out[0] = s * (1.0f / (float)NROWS);
    }
}

extern "C" void kernel_launch(void* const* d_in, const int* in_sizes, int n_in,
                              void* d_out, int out_size) {
    const float* preds   = (const float*)d_in[0];
    const float* targets = (const float*)d_in[1];
    float* out = (float*)d_out;

    pixcorr_row_kernel<<<NROWS, THREADS>>>(preds, targets);

    // Launch the mean kernel with programmatic stream serialization so its
    // launch overhead overlaps the row kernel's execution.
    cudaLaunchConfig_t cfg = {};
    cfg.gridDim  = dim3(1, 1, 1);
    cfg.blockDim = dim3(NROWS, 1, 1);
    cfg.dynamicSmemBytes = 0;
    cfg.stream = 0;  // legacy default stream (same as <<<>>> above)
    cudaLaunchAttribute attr[1];
    attr[0].id = cudaLaunchAttributeProgrammaticStreamSerialization;
    attr[0].val.programmaticStreamSerializationAllowed = 1;
    cfg.attrs = attr;
    cfg.numAttrs = 1;

    cudaError_t e = cudaLaunchKernelEx(&cfg, pixcorr_mean_kernel, out);
    if (e != cudaSuccess) {
        // Fallback: plain serialized launch (identical semantics).
        pixcorr_mean_kernel<<<1, NROWS>>>(out);
    }
}